// round 1
// baseline (speedup 1.0000x reference)
#include <cuda_runtime.h>
#include <math.h>

#define KNOTS 2048
#define WCOLS 7168          // 7 paths * 32 u * 32 w
#define MAXN  4096
#define MAXE  32768

// ---------------- scratch (device globals; no allocation allowed) ----------------
__device__ float g_wtab[(size_t)KNOTS * WCOLS];   // interpolation table, scales folded in
__device__ float g_nodeacc[MAXN * 161];           // 160 sums + 1 count per node
__device__ int   g_binCount[KNOTS];
__device__ int   g_binCursor[KNOTS];
__device__ int   g_perm[MAXE];

// ---------------- constants ----------------
__device__ __forceinline__ int cell_of(float L) {
    float t = L * ((float)(KNOTS - 1) / 5.0f);
    int i = (int)floorf(t);
    if (i < 0) i = 0;
    if (i > KNOTS - 2) i = KNOTS - 2;
    return i;
}

// ---------------- kernel 0: zero accumulators + histogram ----------------
__global__ void k_zero(int total) {
    int i = blockIdx.x * blockDim.x + threadIdx.x;
    if (i < total) g_nodeacc[i] = 0.0f;
    if (i < KNOTS) g_binCount[i] = 0;
}

// ---------------- kernel 1: build W(r) table ----------------
// Table row k (at r = k*5/2047) = silu(radial(r) @ W_fc1/sqrt(8)) @ (W_fc2/8),
// additionally scaled by A0=1/8 (paths 0-3) or A1=sqrt(3/96) (paths 4-6).
__global__ void k_build(const float* __restrict__ Wfc1, const float* __restrict__ Wfc2) {
    __shared__ float sm_h[64][16];   // [c][knot-in-group]
    const int t = threadIdx.x;       // 256 threads
    const int kbase = blockIdx.x * 16;

    // phase 1: h for 16 knots
    for (int idx = t; idx < 16 * 64; idx += 256) {
        int kk = idx >> 6, c = idx & 63;
        float r = (float)(kbase + kk) * (5.0f / (float)(KNOTS - 1));
        float pre = 0.0f;
        #pragma unroll
        for (int j = 0; j < 8; j++) {
            float d = r - (float)j * (5.0f / 7.0f);
            float rad = expf(-d * d * 0.98f);          // 1/(2*sigma^2) = 49/50
            pre += rad * Wfc1[j * 64 + c];
        }
        pre *= 0.35355339059327373f;                    // 1/sqrt(8)
        sm_h[c][kk] = pre / (1.0f + expf(-pre));        // silu
    }
    __syncthreads();

    // phase 2: GEMM h[16,64] @ Wfc2[64,7168]
    for (int colb = 0; colb < WCOLS; colb += 256) {
        int col = colb + t;
        float acc[16];
        #pragma unroll
        for (int kk = 0; kk < 16; kk++) acc[kk] = 0.0f;
        #pragma unroll 4
        for (int c = 0; c < 64; c++) {
            float wv = __ldg(&Wfc2[c * WCOLS + col]);
            #pragma unroll
            for (int kk = 0; kk < 16; kk++) acc[kk] += sm_h[c][kk] * wv;
        }
        int p = col >> 10;
        // (1/8 weight-norm) * (A0 or A1)
        float sc = (p < 4) ? 0.015625f : 0.022097086912079608f;
        #pragma unroll
        for (int kk = 0; kk < 16; kk++)
            g_wtab[(size_t)(kbase + kk) * WCOLS + col] = acc[kk] * sc;
    }
}

// ---------------- sort kernels (counting sort by interp cell) ----------------
__global__ void k_hist(const float* __restrict__ len, int E) {
    int e = blockIdx.x * blockDim.x + threadIdx.x;
    if (e >= E) return;
    atomicAdd(&g_binCount[cell_of(len[e])], 1);
}

__global__ void k_scan() {
    // 1 block, 1024 threads, 2048 bins (2 per thread)
    __shared__ int warpsum[32];
    int t = threadIdx.x;
    int v0 = g_binCount[2 * t], v1 = g_binCount[2 * t + 1];
    int s = v0 + v1;
    int lane = t & 31, wid = t >> 5;
    int x = s;
    #pragma unroll
    for (int o = 1; o < 32; o <<= 1) {
        int y = __shfl_up_sync(0xffffffffu, x, o);
        if (lane >= o) x += y;
    }
    if (lane == 31) warpsum[wid] = x;
    __syncthreads();
    if (wid == 0) {
        int y = warpsum[lane];
        #pragma unroll
        for (int o = 1; o < 32; o <<= 1) {
            int z = __shfl_up_sync(0xffffffffu, y, o);
            if (lane >= o) y += z;
        }
        warpsum[lane] = y;
    }
    __syncthreads();
    int incl = x + (wid > 0 ? warpsum[wid - 1] : 0);
    int excl = incl - s;
    g_binCursor[2 * t]     = excl;
    g_binCursor[2 * t + 1] = excl + v0;
}

__global__ void k_scatter(const float* __restrict__ len, int E) {
    int e = blockIdx.x * blockDim.x + threadIdx.x;
    if (e >= E) return;
    int pos = atomicAdd(&g_binCursor[cell_of(len[e])], 1);
    g_perm[pos] = e;
}

// ---------------- main edge kernel ----------------
// 1 warp per edge; lane = (wg = lane&7 -> 4 consecutive w; us = lane>>3 -> u stride 4).
__global__ void k_edge(const float* __restrict__ x, const float* __restrict__ attr,
                       const float* __restrict__ len, const int* __restrict__ src,
                       const int* __restrict__ dst, int E) {
    __shared__ float tf[8][32][13];   // [warp][u][11 features], stride 13 (conflict-free)
    const int warp = threadIdx.x >> 5, lane = threadIdx.x & 31;
    int eidx = blockIdx.x * 8 + warp;
    if (eidx >= E) return;
    int e = g_perm[eidx];

    int sn = src[e], dn = dst[e];
    float L = len[e];
    const float* ar = attr + e * 9;
    float y0  = ar[0];
    float y10 = ar[1], y11 = ar[2], y12 = ar[3];
    float y20 = ar[4], y21 = ar[5], y22 = ar[6], y23 = ar[7], y24 = ar[8];

    // M[i][k] = sum_m C121[i,m,k]*y2[m]  (constants folded)
    const float cA = 0.31622776601683794f;   // 1/sqrt(10)
    const float cB = 0.18257418583505536f;   // 1/sqrt(30)
    const float cC = 0.36514837167011072f;   // 2/sqrt(30)
    float M00 = -cB * y22 + cA * y24;
    float M01 =  cA * y20,  M02 = cA * y23;
    float M10 =  cA * y20,  M11 = -cB * y22 - cA * y24, M12 = cA * y21;
    float M20 =  cA * y23,  M21 = cA * y21,             M22 = cC * y22;

    // t-features: lane = u for this phase
    const float* xr = x + (size_t)sn * 128;
    float sj = xr[lane];
    float v0 = xr[32 + 3 * lane], v1 = xr[33 + 3 * lane], v2 = xr[34 + 3 * lane];
    const float IS3 = 0.5773502691896258f;
    float* tr = &tf[warp][lane][0];
    tr[0]  = sj * y0;                                    // t00
    tr[1]  = (v0 * y10 + v1 * y11 + v2 * y12) * IS3;     // t11
    float sy = sj * IS3;
    tr[2]  = sy * y10; tr[3] = sy * y11; tr[4] = sy * y12;   // t01[k]
    float yv = y0 * IS3;
    tr[5]  = v0 * yv;  tr[6] = v1 * yv;  tr[7] = v2 * yv;    // t10[k]
    tr[8]  = v0 * M00 + v1 * M10 + v2 * M20;                 // t12[k]
    tr[9]  = v0 * M01 + v1 * M11 + v2 * M21;
    tr[10] = v0 * M02 + v1 * M12 + v2 * M22;
    __syncwarp();

    // interpolation setup (uniform across warp)
    float tp = L * ((float)(KNOTS - 1) / 5.0f);
    int ci = (int)floorf(tp);
    if (ci < 0) ci = 0;
    if (ci > KNOTS - 2) ci = KNOTS - 2;
    float f = tp - (float)ci;
    const float* r0 = g_wtab + (size_t)ci * WCOLS;
    const float* r1 = r0 + WCOLS;

    const int wg = lane & 7, us = lane >> 3;
    const int wb = wg * 4;

    float4 aS  = make_float4(0.f, 0.f, 0.f, 0.f);
    float4 aG  = aS, aV0 = aS, aV1 = aS, aV2 = aS;

#define LERP4(off, V)                                                     \
    {                                                                     \
        float4 _a = *reinterpret_cast<const float4*>(r0 + (off));         \
        float4 _b = *reinterpret_cast<const float4*>(r1 + (off));         \
        V.x = fmaf(f, _b.x - _a.x, _a.x);                                 \
        V.y = fmaf(f, _b.y - _a.y, _a.y);                                 \
        V.z = fmaf(f, _b.z - _a.z, _a.z);                                 \
        V.w = fmaf(f, _b.w - _a.w, _a.w);                                 \
    }
#define FMA4(acc, s, V)                                                   \
    acc.x = fmaf((s), V.x, acc.x); acc.y = fmaf((s), V.y, acc.y);         \
    acc.z = fmaf((s), V.z, acc.z); acc.w = fmaf((s), V.w, acc.w);

    #pragma unroll 2
    for (int j = 0; j < 8; j++) {
        int u = 4 * j + us;
        const float* tv = &tf[warp][u][0];
        float t00 = tv[0], t11 = tv[1];
        float t01a = tv[2], t01b = tv[3], t01c = tv[4];
        float t10a = tv[5], t10b = tv[6], t10c = tv[7];
        float t12a = tv[8], t12b = tv[9], t12c = tv[10];
        int ub = u * 32 + wb;
        float4 v;
        LERP4(0 * 1024 + ub, v); FMA4(aS, t00, v);
        LERP4(1 * 1024 + ub, v); FMA4(aS, t11, v);
        LERP4(2 * 1024 + ub, v); FMA4(aG, t00, v);
        LERP4(3 * 1024 + ub, v); FMA4(aG, t11, v);
        LERP4(4 * 1024 + ub, v); FMA4(aV0, t01a, v); FMA4(aV1, t01b, v); FMA4(aV2, t01c, v);
        LERP4(5 * 1024 + ub, v); FMA4(aV0, t10a, v); FMA4(aV1, t10b, v); FMA4(aV2, t10c, v);
        LERP4(6 * 1024 + ub, v); FMA4(aV0, t12a, v); FMA4(aV1, t12b, v); FMA4(aV2, t12c, v);
    }

#define RED(v)                                                    \
    v += __shfl_down_sync(0xffffffffu, v, 16);                    \
    v += __shfl_down_sync(0xffffffffu, v, 8);
    RED(aS.x)  RED(aS.y)  RED(aS.z)  RED(aS.w)
    RED(aG.x)  RED(aG.y)  RED(aG.z)  RED(aG.w)
    RED(aV0.x) RED(aV0.y) RED(aV0.z) RED(aV0.w)
    RED(aV1.x) RED(aV1.y) RED(aV1.z) RED(aV1.w)
    RED(aV2.x) RED(aV2.y) RED(aV2.z) RED(aV2.w)

    if (us == 0) {
        float* na = g_nodeacc + (size_t)dn * 161;
        float S[4]  = {aS.x, aS.y, aS.z, aS.w};
        float G[4]  = {aG.x, aG.y, aG.z, aG.w};
        float V0[4] = {aV0.x, aV0.y, aV0.z, aV0.w};
        float V1[4] = {aV1.x, aV1.y, aV1.z, aV1.w};
        float V2[4] = {aV2.x, aV2.y, aV2.z, aV2.w};
        #pragma unroll
        for (int q = 0; q < 4; q++) {
            int w = wb + q;
            atomicAdd(na + w,              S[q]);
            atomicAdd(na + 32 + w,         G[q]);
            atomicAdd(na + 64 + 3 * w + 0, V0[q]);
            atomicAdd(na + 64 + 3 * w + 1, V1[q]);
            atomicAdd(na + 64 + 3 * w + 2, V2[q]);
        }
        if (lane == 0) atomicAdd(na + 160, 1.0f);
    }
}

// ---------------- node kernel: mean, gating, self-connection, norms ----------------
__global__ void k_node(const float* __restrict__ x, const float* __restrict__ Wss,
                       const float* __restrict__ Wsv, float* __restrict__ out, int N) {
    __shared__ float sx[8][128];
    const int warp = threadIdx.x >> 5, lane = threadIdx.x & 31;
    int n = blockIdx.x * 8 + warp;
    if (n >= N) return;

    const float4* xr = reinterpret_cast<const float4*>(x + (size_t)n * 128);
    reinterpret_cast<float4*>(&sx[warp][0])[lane] = xr[lane];
    __syncwarp();

    const float* na = g_nodeacc + (size_t)n * 161;
    float inv = 1.0f / fmaxf(na[160], 1.0f);
    float ms  = na[lane] * inv;
    float mg  = na[32 + lane] * inv;
    float mv0 = na[64 + 3 * lane + 0] * inv;
    float mv1 = na[64 + 3 * lane + 1] * inv;
    float mv2 = na[64 + 3 * lane + 2] * inv;

    float gs   = ms / (1.0f + expf(-ms));
    float gate = 1.0f / (1.0f + expf(-mg));
    float gv0 = mv0 * gate, gv1 = mv1 * gate, gv2 = mv2 * gate;

    float ds = 0.f, dv0 = 0.f, dv1 = 0.f, dv2 = 0.f;
    #pragma unroll 4
    for (int u = 0; u < 32; u++) {
        float su  = sx[warp][u];
        float vu0 = sx[warp][32 + 3 * u], vu1 = sx[warp][33 + 3 * u], vu2 = sx[warp][34 + 3 * u];
        float a = __ldg(&Wss[u * 32 + lane]);
        float b = __ldg(&Wsv[u * 32 + lane]);
        ds  = fmaf(su,  a, ds);
        dv0 = fmaf(vu0, b, dv0);
        dv1 = fmaf(vu1, b, dv1);
        dv2 = fmaf(vu2, b, dv2);
    }
    const float ism = 0.17677669529663687f;   // 1/sqrt(32)
    float hs  = gs  + ds  * ism;
    float hv0 = gv0 + dv0 * ism;
    float hv1 = gv1 + dv1 * ism;
    float hv2 = gv2 + dv2 * ism;

    out[(size_t)n * 64 + lane]      = sqrtf(hs * hs + 1e-12f);
    out[(size_t)n * 64 + 32 + lane] = sqrtf(hv0 * hv0 + hv1 * hv1 + hv2 * hv2 + 1e-12f);
}

// ---------------- launch ----------------
extern "C" void kernel_launch(void* const* d_in, const int* in_sizes, int n_in,
                              void* d_out, int out_size) {
    const float* x    = (const float*)d_in[0];
    const float* attr = (const float*)d_in[1];
    const float* len  = (const float*)d_in[2];
    const int*   src  = (const int*)d_in[3];
    const int*   dst  = (const int*)d_in[4];
    const float* Wfc1 = (const float*)d_in[5];
    const float* Wfc2 = (const float*)d_in[6];
    const float* Wss  = (const float*)d_in[7];
    const float* Wsv  = (const float*)d_in[8];
    float* out = (float*)d_out;

    int N = in_sizes[0] / 128;
    int E = in_sizes[2];

    int zt = N * 161;
    if (zt < KNOTS) zt = KNOTS;
    k_zero<<<(zt + 255) / 256, 256>>>(N * 161);
    k_build<<<KNOTS / 16, 256>>>(Wfc1, Wfc2);
    k_hist<<<(E + 255) / 256, 256>>>(len, E);
    k_scan<<<1, 1024>>>();
    k_scatter<<<(E + 255) / 256, 256>>>(len, E);
    k_edge<<<(E + 7) / 8, 256>>>(x, attr, len, src, dst, E);
    k_node<<<(N + 7) / 8, 256>>>(x, Wss, Wsv, out, N);
}

// round 2
// speedup vs baseline: 1.7225x; 1.7225x over previous
#include <cuda_runtime.h>
#include <math.h>

#define KNOTS 256
#define WCOLS 7168          // 7 paths * 32 u * 32 w
#define MAXN  4096
#define MAXE  32768

// ---------------- scratch (device globals; no allocation allowed) ----------------
__device__ float g_wtab[(size_t)KNOTS * WCOLS];   // interpolation table, scales folded in
__device__ float g_nodeacc[MAXN * 161];           // 160 sums + 1 count per node
__device__ int   g_binCount[KNOTS];
__device__ int   g_binCursor[KNOTS];
__device__ int   g_perm[MAXE];

// ---------------- constants ----------------
__device__ __forceinline__ int cell_of(float L) {
    float t = L * ((float)(KNOTS - 1) / 5.0f);
    int i = (int)floorf(t);
    if (i < 0) i = 0;
    if (i > KNOTS - 2) i = KNOTS - 2;
    return i;
}

// ---------------- kernel 0: zero accumulators + bin counts ----------------
__global__ void k_zero(int total) {
    int i = blockIdx.x * blockDim.x + threadIdx.x;
    if (i < total) g_nodeacc[i] = 0.0f;
    if (i < KNOTS) g_binCount[i] = 0;
}

// ---------------- kernel 1: build W(r) table ----------------
// Table row k (at r = k*5/(KNOTS-1)) = silu(radial(r) @ W_fc1/sqrt(8)) @ (W_fc2/8),
// additionally scaled by A0=1/8 (paths 0-3) or A1=sqrt(3/96) (paths 4-6).
// Grid: (KNOTS/16, 7). Block handles 16 knots x 1024 cols; each thread 2 cols x 16 knots.
__global__ void k_build(const float* __restrict__ Wfc1, const float* __restrict__ Wfc2) {
    __shared__ float sm_h[64][17];   // [c][knot-in-group], padded
    const int t = threadIdx.x;       // 256 threads
    const int kbase = blockIdx.x * 16;
    const int cbase = blockIdx.y * 1024;

    // phase 1: h for 16 knots
    for (int idx = t; idx < 16 * 64; idx += 256) {
        int kk = idx >> 6, c = idx & 63;
        float r = (float)(kbase + kk) * (5.0f / (float)(KNOTS - 1));
        float pre = 0.0f;
        #pragma unroll
        for (int j = 0; j < 8; j++) {
            float d = r - (float)j * (5.0f / 7.0f);
            float rad = expf(-d * d * 0.98f);          // 1/(2*sigma^2) = 49/50
            pre += rad * Wfc1[j * 64 + c];
        }
        pre *= 0.35355339059327373f;                    // 1/sqrt(8)
        sm_h[c][kk] = pre / (1.0f + expf(-pre));        // silu
    }
    __syncthreads();

    // phase 2: GEMM h[16,64] @ Wfc2[64, 1024-slab]; 2 cols per thread per iter
    #pragma unroll
    for (int it = 0; it < 2; it++) {
        int col0 = cbase + it * 512 + t;        // thread's first col
        int col1 = col0 + 256;                  // thread's second col
        float a0[16], a1[16];
        #pragma unroll
        for (int kk = 0; kk < 16; kk++) { a0[kk] = 0.0f; a1[kk] = 0.0f; }
        #pragma unroll 4
        for (int c = 0; c < 64; c++) {
            float w0 = __ldg(&Wfc2[c * WCOLS + col0]);
            float w1 = __ldg(&Wfc2[c * WCOLS + col1]);
            #pragma unroll
            for (int kk = 0; kk < 16; kk++) {
                float hv = sm_h[c][kk];
                a0[kk] = fmaf(hv, w0, a0[kk]);
                a1[kk] = fmaf(hv, w1, a1[kk]);
            }
        }
        float s0 = (col0 < 4096) ? 0.015625f : 0.022097086912079608f;
        float s1 = (col1 < 4096) ? 0.015625f : 0.022097086912079608f;
        #pragma unroll
        for (int kk = 0; kk < 16; kk++) {
            g_wtab[(size_t)(kbase + kk) * WCOLS + col0] = a0[kk] * s0;
            g_wtab[(size_t)(kbase + kk) * WCOLS + col1] = a1[kk] * s1;
        }
    }
}

// ---------------- sort kernels (counting sort by interp cell) ----------------
__global__ void k_hist(const float* __restrict__ len, int E) {
    int e = blockIdx.x * blockDim.x + threadIdx.x;
    if (e >= E) return;
    atomicAdd(&g_binCount[cell_of(len[e])], 1);
}

__global__ void k_scan() {
    // 1 block, 256 threads, 256 bins
    __shared__ int wsum[8];
    int t = threadIdx.x;
    int v = g_binCount[t];
    int lane = t & 31, wid = t >> 5;
    int x = v;
    #pragma unroll
    for (int o = 1; o < 32; o <<= 1) {
        int y = __shfl_up_sync(0xffffffffu, x, o);
        if (lane >= o) x += y;
    }
    if (lane == 31) wsum[wid] = x;
    __syncthreads();
    if (wid == 0 && lane < 8) {
        int y = wsum[lane];
        #pragma unroll
        for (int o = 1; o < 8; o <<= 1) {
            int z = __shfl_up_sync(0x000000ffu, y, o);
            if (lane >= o) y += z;
        }
        wsum[lane] = y;
    }
    __syncthreads();
    int incl = x + (wid > 0 ? wsum[wid - 1] : 0);
    g_binCursor[t] = incl - v;   // exclusive
}

__global__ void k_scatter(const float* __restrict__ len, int E) {
    int e = blockIdx.x * blockDim.x + threadIdx.x;
    if (e >= E) return;
    int pos = atomicAdd(&g_binCursor[cell_of(len[e])], 1);
    g_perm[pos] = e;
}

// ---------------- main edge kernel ----------------
// 1 warp per edge; lane = (wg = lane&7 -> 4 consecutive w; us = lane>>3 -> u stride 4).
__global__ void k_edge(const float* __restrict__ x, const float* __restrict__ attr,
                       const float* __restrict__ len, const int* __restrict__ src,
                       const int* __restrict__ dst, int E) {
    __shared__ float tf[8][32][13];   // [warp][u][11 features], stride 13 (conflict-free)
    const int warp = threadIdx.x >> 5, lane = threadIdx.x & 31;
    int eidx = blockIdx.x * 8 + warp;
    if (eidx >= E) return;
    int e = g_perm[eidx];

    int sn = src[e], dn = dst[e];
    float L = len[e];
    const float* ar = attr + e * 9;
    float y0  = ar[0];
    float y10 = ar[1], y11 = ar[2], y12 = ar[3];
    float y20 = ar[4], y21 = ar[5], y22 = ar[6], y23 = ar[7], y24 = ar[8];

    // M[i][k] = sum_m C121[i,m,k]*y2[m]  (constants folded)
    const float cA = 0.31622776601683794f;   // 1/sqrt(10)
    const float cB = 0.18257418583505536f;   // 1/sqrt(30)
    const float cC = 0.36514837167011072f;   // 2/sqrt(30)
    float M00 = -cB * y22 + cA * y24;
    float M01 =  cA * y20,  M02 = cA * y23;
    float M10 =  cA * y20,  M11 = -cB * y22 - cA * y24, M12 = cA * y21;
    float M20 =  cA * y23,  M21 = cA * y21,             M22 = cC * y22;

    // t-features: lane = u for this phase
    const float* xr = x + (size_t)sn * 128;
    float sj = xr[lane];
    float v0 = xr[32 + 3 * lane], v1 = xr[33 + 3 * lane], v2 = xr[34 + 3 * lane];
    const float IS3 = 0.5773502691896258f;
    float* tr = &tf[warp][lane][0];
    tr[0]  = sj * y0;                                    // t00
    tr[1]  = (v0 * y10 + v1 * y11 + v2 * y12) * IS3;     // t11
    float sy = sj * IS3;
    tr[2]  = sy * y10; tr[3] = sy * y11; tr[4] = sy * y12;   // t01[k]
    float yv = y0 * IS3;
    tr[5]  = v0 * yv;  tr[6] = v1 * yv;  tr[7] = v2 * yv;    // t10[k]
    tr[8]  = v0 * M00 + v1 * M10 + v2 * M20;                 // t12[k]
    tr[9]  = v0 * M01 + v1 * M11 + v2 * M21;
    tr[10] = v0 * M02 + v1 * M12 + v2 * M22;
    __syncwarp();

    // interpolation setup (uniform across warp)
    float tp = L * ((float)(KNOTS - 1) / 5.0f);
    int ci = (int)floorf(tp);
    if (ci < 0) ci = 0;
    if (ci > KNOTS - 2) ci = KNOTS - 2;
    float f = tp - (float)ci;
    const float* r0 = g_wtab + (size_t)ci * WCOLS;
    const float* r1 = r0 + WCOLS;

    const int wg = lane & 7, us = lane >> 3;
    const int wb = wg * 4;

    float4 aS  = make_float4(0.f, 0.f, 0.f, 0.f);
    float4 aG  = aS, aV0 = aS, aV1 = aS, aV2 = aS;

#define LERP4(off, V)                                                     \
    {                                                                     \
        float4 _a = *reinterpret_cast<const float4*>(r0 + (off));         \
        float4 _b = *reinterpret_cast<const float4*>(r1 + (off));         \
        V.x = fmaf(f, _b.x - _a.x, _a.x);                                 \
        V.y = fmaf(f, _b.y - _a.y, _a.y);                                 \
        V.z = fmaf(f, _b.z - _a.z, _a.z);                                 \
        V.w = fmaf(f, _b.w - _a.w, _a.w);                                 \
    }
#define FMA4(acc, s, V)                                                   \
    acc.x = fmaf((s), V.x, acc.x); acc.y = fmaf((s), V.y, acc.y);         \
    acc.z = fmaf((s), V.z, acc.z); acc.w = fmaf((s), V.w, acc.w);

    #pragma unroll 2
    for (int j = 0; j < 8; j++) {
        int u = 4 * j + us;
        const float* tv = &tf[warp][u][0];
        float t00 = tv[0], t11 = tv[1];
        float t01a = tv[2], t01b = tv[3], t01c = tv[4];
        float t10a = tv[5], t10b = tv[6], t10c = tv[7];
        float t12a = tv[8], t12b = tv[9], t12c = tv[10];
        int ub = u * 32 + wb;
        float4 v;
        LERP4(0 * 1024 + ub, v); FMA4(aS, t00, v);
        LERP4(1 * 1024 + ub, v); FMA4(aS, t11, v);
        LERP4(2 * 1024 + ub, v); FMA4(aG, t00, v);
        LERP4(3 * 1024 + ub, v); FMA4(aG, t11, v);
        LERP4(4 * 1024 + ub, v); FMA4(aV0, t01a, v); FMA4(aV1, t01b, v); FMA4(aV2, t01c, v);
        LERP4(5 * 1024 + ub, v); FMA4(aV0, t10a, v); FMA4(aV1, t10b, v); FMA4(aV2, t10c, v);
        LERP4(6 * 1024 + ub, v); FMA4(aV0, t12a, v); FMA4(aV1, t12b, v); FMA4(aV2, t12c, v);
    }

#define RED(v)                                                    \
    v += __shfl_down_sync(0xffffffffu, v, 16);                    \
    v += __shfl_down_sync(0xffffffffu, v, 8);
    RED(aS.x)  RED(aS.y)  RED(aS.z)  RED(aS.w)
    RED(aG.x)  RED(aG.y)  RED(aG.z)  RED(aG.w)
    RED(aV0.x) RED(aV0.y) RED(aV0.z) RED(aV0.w)
    RED(aV1.x) RED(aV1.y) RED(aV1.z) RED(aV1.w)
    RED(aV2.x) RED(aV2.y) RED(aV2.z) RED(aV2.w)

    if (us == 0) {
        float* na = g_nodeacc + (size_t)dn * 161;
        float S[4]  = {aS.x, aS.y, aS.z, aS.w};
        float G[4]  = {aG.x, aG.y, aG.z, aG.w};
        float V0[4] = {aV0.x, aV0.y, aV0.z, aV0.w};
        float V1[4] = {aV1.x, aV1.y, aV1.z, aV1.w};
        float V2[4] = {aV2.x, aV2.y, aV2.z, aV2.w};
        #pragma unroll
        for (int q = 0; q < 4; q++) {
            int w = wb + q;
            atomicAdd(na + w,              S[q]);
            atomicAdd(na + 32 + w,         G[q]);
            atomicAdd(na + 64 + 3 * w + 0, V0[q]);
            atomicAdd(na + 64 + 3 * w + 1, V1[q]);
            atomicAdd(na + 64 + 3 * w + 2, V2[q]);
        }
        if (lane == 0) atomicAdd(na + 160, 1.0f);
    }
}

// ---------------- node kernel: mean, gating, self-connection, norms ----------------
__global__ void k_node(const float* __restrict__ x, const float* __restrict__ Wss,
                       const float* __restrict__ Wsv, float* __restrict__ out, int N) {
    __shared__ float sx[8][128];
    const int warp = threadIdx.x >> 5, lane = threadIdx.x & 31;
    int n = blockIdx.x * 8 + warp;
    if (n >= N) return;

    const float4* xr = reinterpret_cast<const float4*>(x + (size_t)n * 128);
    reinterpret_cast<float4*>(&sx[warp][0])[lane] = xr[lane];
    __syncwarp();

    const float* na = g_nodeacc + (size_t)n * 161;
    float inv = 1.0f / fmaxf(na[160], 1.0f);
    float ms  = na[lane] * inv;
    float mg  = na[32 + lane] * inv;
    float mv0 = na[64 + 3 * lane + 0] * inv;
    float mv1 = na[64 + 3 * lane + 1] * inv;
    float mv2 = na[64 + 3 * lane + 2] * inv;

    float gs   = ms / (1.0f + expf(-ms));
    float gate = 1.0f / (1.0f + expf(-mg));
    float gv0 = mv0 * gate, gv1 = mv1 * gate, gv2 = mv2 * gate;

    float ds = 0.f, dv0 = 0.f, dv1 = 0.f, dv2 = 0.f;
    #pragma unroll 4
    for (int u = 0; u < 32; u++) {
        float su  = sx[warp][u];
        float vu0 = sx[warp][32 + 3 * u], vu1 = sx[warp][33 + 3 * u], vu2 = sx[warp][34 + 3 * u];
        float a = __ldg(&Wss[u * 32 + lane]);
        float b = __ldg(&Wsv[u * 32 + lane]);
        ds  = fmaf(su,  a, ds);
        dv0 = fmaf(vu0, b, dv0);
        dv1 = fmaf(vu1, b, dv1);
        dv2 = fmaf(vu2, b, dv2);
    }
    const float ism = 0.17677669529663687f;   // 1/sqrt(32)
    float hs  = gs  + ds  * ism;
    float hv0 = gv0 + dv0 * ism;
    float hv1 = gv1 + dv1 * ism;
    float hv2 = gv2 + dv2 * ism;

    out[(size_t)n * 64 + lane]      = sqrtf(hs * hs + 1e-12f);
    out[(size_t)n * 64 + 32 + lane] = sqrtf(hv0 * hv0 + hv1 * hv1 + hv2 * hv2 + 1e-12f);
}

// ---------------- launch ----------------
extern "C" void kernel_launch(void* const* d_in, const int* in_sizes, int n_in,
                              void* d_out, int out_size) {
    const float* x    = (const float*)d_in[0];
    const float* attr = (const float*)d_in[1];
    const float* len  = (const float*)d_in[2];
    const int*   src  = (const int*)d_in[3];
    const int*   dst  = (const int*)d_in[4];
    const float* Wfc1 = (const float*)d_in[5];
    const float* Wfc2 = (const float*)d_in[6];
    const float* Wss  = (const float*)d_in[7];
    const float* Wsv  = (const float*)d_in[8];
    float* out = (float*)d_out;

    int N = in_sizes[0] / 128;
    int E = in_sizes[2];

    int zt = N * 161;
    if (zt < KNOTS) zt = KNOTS;
    k_zero<<<(zt + 255) / 256, 256>>>(N * 161);
    dim3 bgrid(KNOTS / 16, 7);
    k_build<<<bgrid, 256>>>(Wfc1, Wfc2);
    k_hist<<<(E + 255) / 256, 256>>>(len, E);
    k_scan<<<1, 256>>>();
    k_scatter<<<(E + 255) / 256, 256>>>(len, E);
    k_edge<<<(E + 7) / 8, 256>>>(x, attr, len, src, dst, E);
    k_node<<<(N + 7) / 8, 256>>>(x, Wss, Wsv, out, N);
}

// round 3
// speedup vs baseline: 2.1332x; 1.2385x over previous
#include <cuda_runtime.h>
#include <cuda_fp16.h>
#include <math.h>

#define KNOTS 64
#define WCOLS 7168          // 7 paths * 32 u * 32 w
#define MAXN  4096
#define MAXE  32768

// ---------------- scratch (device globals; no allocation allowed) ----------------
__device__ unsigned short g_wtab_raw[(size_t)KNOTS * WCOLS];  // fp16 table, scales folded in
__device__ float g_nodeacc[MAXN * 161];           // 160 sums + 1 count per node
__device__ int   g_binCount[KNOTS];
__device__ int   g_binCursor[KNOTS];
__device__ int   g_perm[MAXE];

// ---------------- f32x2 helpers ----------------
__device__ __forceinline__ unsigned long long pk2(float lo, float hi) {
    unsigned long long r;
    asm("mov.b64 %0, {%1, %2};" : "=l"(r) : "f"(lo), "f"(hi));
    return r;
}
__device__ __forceinline__ void upk2(unsigned long long v, float& lo, float& hi) {
    asm("mov.b64 {%0, %1}, %2;" : "=f"(lo), "=f"(hi) : "l"(v));
}
__device__ __forceinline__ void fma2(unsigned long long& d, unsigned long long a, unsigned long long b) {
    asm("fma.rn.f32x2 %0, %1, %2, %0;" : "+l"(d) : "l"(a), "l"(b));
}
__device__ __forceinline__ unsigned long long mul2(unsigned long long a, unsigned long long b) {
    unsigned long long r;
    asm("mul.rn.f32x2 %0, %1, %2;" : "=l"(r) : "l"(a), "l"(b));
    return r;
}

// ---------------- constants ----------------
__device__ __forceinline__ int cell_of(float L) {
    float t = L * ((float)(KNOTS - 1) / 5.0f);
    int i = (int)floorf(t);
    if (i < 0) i = 0;
    if (i > KNOTS - 2) i = KNOTS - 2;
    return i;
}

// ---------------- kernel 0: zero accumulators + bin counts ----------------
__global__ void k_zero(int total) {
    int i = blockIdx.x * blockDim.x + threadIdx.x;
    if (i < total) g_nodeacc[i] = 0.0f;
    if (i < KNOTS) g_binCount[i] = 0;
}

// ---------------- kernel 1: build fp16 W(r) table ----------------
// Grid: (KNOTS/16, 28). Block: 16 knots x 256 cols, 1 col/thread.
__global__ void k_build(const float* __restrict__ Wfc1, const float* __restrict__ Wfc2) {
    __shared__ float sm_h[64][17];   // [c][knot-in-group], padded
    const int t = threadIdx.x;       // 256 threads
    const int kbase = blockIdx.x * 16;
    const int col = blockIdx.y * 256 + t;

    // phase 1: h for 16 knots
    for (int idx = t; idx < 16 * 64; idx += 256) {
        int kk = idx >> 6, c = idx & 63;
        float r = (float)(kbase + kk) * (5.0f / (float)(KNOTS - 1));
        float pre = 0.0f;
        #pragma unroll
        for (int j = 0; j < 8; j++) {
            float d = r - (float)j * (5.0f / 7.0f);
            float rad = expf(-d * d * 0.98f);          // 1/(2*sigma^2) = 49/50
            pre += rad * Wfc1[j * 64 + c];
        }
        pre *= 0.35355339059327373f;                    // 1/sqrt(8)
        sm_h[c][kk] = pre / (1.0f + expf(-pre));        // silu
    }
    __syncthreads();

    // phase 2: GEMM h[16,64] @ Wfc2[64, col]
    float acc[16];
    #pragma unroll
    for (int kk = 0; kk < 16; kk++) acc[kk] = 0.0f;
    #pragma unroll 4
    for (int c = 0; c < 64; c++) {
        float wv = __ldg(&Wfc2[c * WCOLS + col]);
        #pragma unroll
        for (int kk = 0; kk < 16; kk++) acc[kk] = fmaf(sm_h[c][kk], wv, acc[kk]);
    }
    // (1/8 weight-norm) * (A0 or A1)
    float sc = (col < 4096) ? 0.015625f : 0.022097086912079608f;
    #pragma unroll
    for (int kk = 0; kk < 16; kk++)
        g_wtab_raw[(size_t)(kbase + kk) * WCOLS + col] =
            __half_as_ushort(__float2half_rn(acc[kk] * sc));
}

// ---------------- sort kernels (counting sort by interp cell) ----------------
__global__ void k_hist(const float* __restrict__ len, int E) {
    int e = blockIdx.x * blockDim.x + threadIdx.x;
    if (e >= E) return;
    atomicAdd(&g_binCount[cell_of(len[e])], 1);
}

__global__ void k_scan() {
    // 1 warp, 2 bins per lane (64 bins)
    int t = threadIdx.x;
    int v0 = g_binCount[2 * t], v1 = g_binCount[2 * t + 1];
    int s = v0 + v1;
    int x = s;
    #pragma unroll
    for (int o = 1; o < 32; o <<= 1) {
        int y = __shfl_up_sync(0xffffffffu, x, o);
        if (t >= o) x += y;
    }
    int excl = x - s;
    g_binCursor[2 * t]     = excl;
    g_binCursor[2 * t + 1] = excl + v0;
}

__global__ void k_scatter(const float* __restrict__ len, int E) {
    int e = blockIdx.x * blockDim.x + threadIdx.x;
    if (e >= E) return;
    int pos = atomicAdd(&g_binCursor[cell_of(len[e])], 1);
    g_perm[pos] = e;
}

// ---------------- main edge kernel ----------------
// 1 warp per edge; lane = (wg = lane&7 -> 4 consecutive w; us = lane>>3 -> u stride 4).
// fp16 table, deferred lerp (two acc banks), f32x2 FMA.
__global__ __launch_bounds__(256, 2) void k_edge(
        const float* __restrict__ x, const float* __restrict__ attr,
        const float* __restrict__ len, const int* __restrict__ src,
        const int* __restrict__ dst, int E) {
    __shared__ float2 tf2[8][32][11];   // features pre-duplicated as (v,v)
    const int warp = threadIdx.x >> 5, lane = threadIdx.x & 31;
    int eidx = blockIdx.x * 8 + warp;
    if (eidx >= E) return;
    int e = g_perm[eidx];

    int sn = src[e], dn = dst[e];
    float L = len[e];
    const float* ar = attr + e * 9;
    float y0  = ar[0];
    float y10 = ar[1], y11 = ar[2], y12 = ar[3];
    float y20 = ar[4], y21 = ar[5], y22 = ar[6], y23 = ar[7], y24 = ar[8];

    // M[i][k] = sum_m C121[i,m,k]*y2[m]  (constants folded)
    const float cA = 0.31622776601683794f;   // 1/sqrt(10)
    const float cB = 0.18257418583505536f;   // 1/sqrt(30)
    const float cC = 0.36514837167011072f;   // 2/sqrt(30)
    float M00 = -cB * y22 + cA * y24;
    float M01 =  cA * y20,  M02 = cA * y23;
    float M10 =  cA * y20,  M11 = -cB * y22 - cA * y24, M12 = cA * y21;
    float M20 =  cA * y23,  M21 = cA * y21,             M22 = cC * y22;

    // t-features: lane = u for this phase
    const float* xr = x + (size_t)sn * 128;
    float sj = xr[lane];
    float v0 = xr[32 + 3 * lane], v1 = xr[33 + 3 * lane], v2 = xr[34 + 3 * lane];
    const float IS3 = 0.5773502691896258f;
    float2* tr = &tf2[warp][lane][0];
    float t00 = sj * y0;
    float t11 = (v0 * y10 + v1 * y11 + v2 * y12) * IS3;
    tr[0] = make_float2(t00, t00);
    tr[1] = make_float2(t11, t11);
    float sy = sj * IS3;
    tr[2] = make_float2(sy * y10, sy * y10);
    tr[3] = make_float2(sy * y11, sy * y11);
    tr[4] = make_float2(sy * y12, sy * y12);
    float yv = y0 * IS3;
    tr[5] = make_float2(v0 * yv, v0 * yv);
    tr[6] = make_float2(v1 * yv, v1 * yv);
    tr[7] = make_float2(v2 * yv, v2 * yv);
    float t12a = v0 * M00 + v1 * M10 + v2 * M20;
    float t12b = v0 * M01 + v1 * M11 + v2 * M21;
    float t12c = v0 * M02 + v1 * M12 + v2 * M22;
    tr[8]  = make_float2(t12a, t12a);
    tr[9]  = make_float2(t12b, t12b);
    tr[10] = make_float2(t12c, t12c);
    __syncwarp();

    // interpolation setup (uniform across warp)
    float tp = L * ((float)(KNOTS - 1) / 5.0f);
    int ci = (int)floorf(tp);
    if (ci < 0) ci = 0;
    if (ci > KNOTS - 2) ci = KNOTS - 2;
    float f = tp - (float)ci;
    const __half* wt = reinterpret_cast<const __half*>(g_wtab_raw);
    const __half* r0 = wt + (size_t)ci * WCOLS;
    const __half* r1 = r0 + WCOLS;

    const int wg = lane & 7, us = lane >> 3;
    const int wb = wg * 4;

    // accumulators: [bank(knot)][col-pair]
    unsigned long long aS[2][2]  = {{0ull,0ull},{0ull,0ull}};
    unsigned long long aG[2][2]  = {{0ull,0ull},{0ull,0ull}};
    unsigned long long aV[3][2][2] = {{{0ull,0ull},{0ull,0ull}},
                                      {{0ull,0ull},{0ull,0ull}},
                                      {{0ull,0ull},{0ull,0ull}}};

    #pragma unroll 2
    for (int j = 0; j < 8; j++) {
        int u = 4 * j + us;
        const unsigned long long* Fv =
            reinterpret_cast<const unsigned long long*>(&tf2[warp][u][0]);
        int ub = u * 32 + wb;
        const __half* p0 = r0 + ub;
        const __half* p1 = r1 + ub;
        unsigned long long A0, A1, B0, B1, F;

#define LOADP(P)                                                                  \
        {                                                                         \
            uint2 _a = *reinterpret_cast<const uint2*>(p0 + (P) * 1024);          \
            uint2 _b = *reinterpret_cast<const uint2*>(p1 + (P) * 1024);          \
            float2 _f;                                                            \
            _f = __half22float2(*reinterpret_cast<const __half2*>(&_a.x)); A0 = pk2(_f.x, _f.y); \
            _f = __half22float2(*reinterpret_cast<const __half2*>(&_a.y)); A1 = pk2(_f.x, _f.y); \
            _f = __half22float2(*reinterpret_cast<const __half2*>(&_b.x)); B0 = pk2(_f.x, _f.y); \
            _f = __half22float2(*reinterpret_cast<const __half2*>(&_b.y)); B1 = pk2(_f.x, _f.y); \
        }

        LOADP(0); F = Fv[0];
        fma2(aS[0][0], F, A0); fma2(aS[0][1], F, A1);
        fma2(aS[1][0], F, B0); fma2(aS[1][1], F, B1);
        LOADP(1); F = Fv[1];
        fma2(aS[0][0], F, A0); fma2(aS[0][1], F, A1);
        fma2(aS[1][0], F, B0); fma2(aS[1][1], F, B1);
        LOADP(2); F = Fv[0];
        fma2(aG[0][0], F, A0); fma2(aG[0][1], F, A1);
        fma2(aG[1][0], F, B0); fma2(aG[1][1], F, B1);
        LOADP(3); F = Fv[1];
        fma2(aG[0][0], F, A0); fma2(aG[0][1], F, A1);
        fma2(aG[1][0], F, B0); fma2(aG[1][1], F, B1);
        LOADP(4);
        F = Fv[2]; fma2(aV[0][0][0], F, A0); fma2(aV[0][0][1], F, A1);
                   fma2(aV[0][1][0], F, B0); fma2(aV[0][1][1], F, B1);
        F = Fv[3]; fma2(aV[1][0][0], F, A0); fma2(aV[1][0][1], F, A1);
                   fma2(aV[1][1][0], F, B0); fma2(aV[1][1][1], F, B1);
        F = Fv[4]; fma2(aV[2][0][0], F, A0); fma2(aV[2][0][1], F, A1);
                   fma2(aV[2][1][0], F, B0); fma2(aV[2][1][1], F, B1);
        LOADP(5);
        F = Fv[5]; fma2(aV[0][0][0], F, A0); fma2(aV[0][0][1], F, A1);
                   fma2(aV[0][1][0], F, B0); fma2(aV[0][1][1], F, B1);
        F = Fv[6]; fma2(aV[1][0][0], F, A0); fma2(aV[1][0][1], F, A1);
                   fma2(aV[1][1][0], F, B0); fma2(aV[1][1][1], F, B1);
        F = Fv[7]; fma2(aV[2][0][0], F, A0); fma2(aV[2][0][1], F, A1);
                   fma2(aV[2][1][0], F, B0); fma2(aV[2][1][1], F, B1);
        LOADP(6);
        F = Fv[8]; fma2(aV[0][0][0], F, A0); fma2(aV[0][0][1], F, A1);
                   fma2(aV[0][1][0], F, B0); fma2(aV[0][1][1], F, B1);
        F = Fv[9]; fma2(aV[1][0][0], F, A0); fma2(aV[1][0][1], F, A1);
                   fma2(aV[1][1][0], F, B0); fma2(aV[1][1][1], F, B1);
        F = Fv[10]; fma2(aV[2][0][0], F, A0); fma2(aV[2][0][1], F, A1);
                    fma2(aV[2][1][0], F, B0); fma2(aV[2][1][1], F, B1);
#undef LOADP
    }

    // combine banks: m = (1-f)*bank0 + f*bank1
    unsigned long long f2  = pk2(f, f);
    unsigned long long g2  = pk2(1.0f - f, 1.0f - f);
    float S[4], G[4], V[3][4];
    {
        unsigned long long m;
        m = mul2(g2, aS[0][0]); fma2(m, f2, aS[1][0]); upk2(m, S[0], S[1]);
        m = mul2(g2, aS[0][1]); fma2(m, f2, aS[1][1]); upk2(m, S[2], S[3]);
        m = mul2(g2, aG[0][0]); fma2(m, f2, aG[1][0]); upk2(m, G[0], G[1]);
        m = mul2(g2, aG[0][1]); fma2(m, f2, aG[1][1]); upk2(m, G[2], G[3]);
        #pragma unroll
        for (int k = 0; k < 3; k++) {
            m = mul2(g2, aV[k][0][0]); fma2(m, f2, aV[k][1][0]); upk2(m, V[k][0], V[k][1]);
            m = mul2(g2, aV[k][0][1]); fma2(m, f2, aV[k][1][1]); upk2(m, V[k][2], V[k][3]);
        }
    }

#define RED(v)                                                    \
    v += __shfl_down_sync(0xffffffffu, v, 16);                    \
    v += __shfl_down_sync(0xffffffffu, v, 8);
    #pragma unroll
    for (int q = 0; q < 4; q++) {
        RED(S[q]) RED(G[q]) RED(V[0][q]) RED(V[1][q]) RED(V[2][q])
    }

    if (us == 0) {
        float* na = g_nodeacc + (size_t)dn * 161;
        #pragma unroll
        for (int q = 0; q < 4; q++) {
            int w = wb + q;
            atomicAdd(na + w,              S[q]);
            atomicAdd(na + 32 + w,         G[q]);
            atomicAdd(na + 64 + 3 * w + 0, V[0][q]);
            atomicAdd(na + 64 + 3 * w + 1, V[1][q]);
            atomicAdd(na + 64 + 3 * w + 2, V[2][q]);
        }
        if (lane == 0) atomicAdd(na + 160, 1.0f);
    }
}

// ---------------- node kernel: mean, gating, self-connection, norms ----------------
__global__ void k_node(const float* __restrict__ x, const float* __restrict__ Wss,
                       const float* __restrict__ Wsv, float* __restrict__ out, int N) {
    __shared__ float sx[8][128];
    const int warp = threadIdx.x >> 5, lane = threadIdx.x & 31;
    int n = blockIdx.x * 8 + warp;
    if (n >= N) return;

    const float4* xr = reinterpret_cast<const float4*>(x + (size_t)n * 128);
    reinterpret_cast<float4*>(&sx[warp][0])[lane] = xr[lane];
    __syncwarp();

    const float* na = g_nodeacc + (size_t)n * 161;
    float inv = 1.0f / fmaxf(na[160], 1.0f);
    float ms  = na[lane] * inv;
    float mg  = na[32 + lane] * inv;
    float mv0 = na[64 + 3 * lane + 0] * inv;
    float mv1 = na[64 + 3 * lane + 1] * inv;
    float mv2 = na[64 + 3 * lane + 2] * inv;

    float gs   = ms / (1.0f + expf(-ms));
    float gate = 1.0f / (1.0f + expf(-mg));
    float gv0 = mv0 * gate, gv1 = mv1 * gate, gv2 = mv2 * gate;

    float ds = 0.f, dv0 = 0.f, dv1 = 0.f, dv2 = 0.f;
    #pragma unroll 4
    for (int u = 0; u < 32; u++) {
        float su  = sx[warp][u];
        float vu0 = sx[warp][32 + 3 * u], vu1 = sx[warp][33 + 3 * u], vu2 = sx[warp][34 + 3 * u];
        float a = __ldg(&Wss[u * 32 + lane]);
        float b = __ldg(&Wsv[u * 32 + lane]);
        ds  = fmaf(su,  a, ds);
        dv0 = fmaf(vu0, b, dv0);
        dv1 = fmaf(vu1, b, dv1);
        dv2 = fmaf(vu2, b, dv2);
    }
    const float ism = 0.17677669529663687f;   // 1/sqrt(32)
    float hs  = gs  + ds  * ism;
    float hv0 = gv0 + dv0 * ism;
    float hv1 = gv1 + dv1 * ism;
    float hv2 = gv2 + dv2 * ism;

    out[(size_t)n * 64 + lane]      = sqrtf(hs * hs + 1e-12f);
    out[(size_t)n * 64 + 32 + lane] = sqrtf(hv0 * hv0 + hv1 * hv1 + hv2 * hv2 + 1e-12f);
}

// ---------------- launch ----------------
extern "C" void kernel_launch(void* const* d_in, const int* in_sizes, int n_in,
                              void* d_out, int out_size) {
    const float* x    = (const float*)d_in[0];
    const float* attr = (const float*)d_in[1];
    const float* len  = (const float*)d_in[2];
    const int*   src  = (const int*)d_in[3];
    const int*   dst  = (const int*)d_in[4];
    const float* Wfc1 = (const float*)d_in[5];
    const float* Wfc2 = (const float*)d_in[6];
    const float* Wss  = (const float*)d_in[7];
    const float* Wsv  = (const float*)d_in[8];
    float* out = (float*)d_out;

    int N = in_sizes[0] / 128;
    int E = in_sizes[2];

    int zt = N * 161;
    if (zt < KNOTS) zt = KNOTS;
    k_zero<<<(zt + 255) / 256, 256>>>(N * 161);
    dim3 bgrid(KNOTS / 16, 28);
    k_build<<<bgrid, 256>>>(Wfc1, Wfc2);
    k_hist<<<(E + 255) / 256, 256>>>(len, E);
    k_scan<<<1, 32>>>();
    k_scatter<<<(E + 255) / 256, 256>>>(len, E);
    k_edge<<<(E + 7) / 8, 256>>>(x, attr, len, src, dst, E);
    k_node<<<(N + 7) / 8, 256>>>(x, Wss, Wsv, out, N);
}